// round 16
// baseline (speedup 1.0000x reference)
#include <cuda_runtime.h>
#include <cuda_bf16.h>

// Haar DWT2: input (8,32,512,512) f32 -> output (8,4,32,256,256) f32
// Subbands: LL, LH, HL, HH (pywt order: LH = highpass along H)
//
// R13: R12 memory shape (8 cols/thread, all ops 256-bit) + software pipeline
// across 2 planes per thread (bc, bc+128). Next tile's loads are issued
// BEFORE current tile's stores, so every warp keeps reads and writes
// simultaneously in flight -> DRAM scheduler can batch same-direction bursts
// and amortize bus turnarounds.

#define H_IN  512
#define W_IN  512
#define H_OUT 256
#define W_OUT 256
#define C_DIM 32
#define B_DIM 8
#define COLS_PER_THREAD 8
#define GROUPS_PER_ROW (W_OUT / COLS_PER_THREAD)   // 32
#define PLANES_PER_THREAD 2
#define BC_STRIDE 128                               // Δbc between the 2 tiles

__device__ __forceinline__ void ldg256(const float* __restrict__ p,
                                       float4& lo, float4& hi)
{
    asm volatile("ld.global.nc.v8.f32 {%0,%1,%2,%3,%4,%5,%6,%7}, [%8];"
                 : "=f"(lo.x), "=f"(lo.y), "=f"(lo.z), "=f"(lo.w),
                   "=f"(hi.x), "=f"(hi.y), "=f"(hi.z), "=f"(hi.w)
                 : "l"(p));
}

__device__ __forceinline__ void stg256(float* __restrict__ p,
                                       const float4& lo, const float4& hi)
{
    asm volatile("st.global.v8.f32 [%0], {%1,%2,%3,%4,%5,%6,%7,%8};"
                 :: "l"(p),
                    "f"(lo.x), "f"(lo.y), "f"(lo.z), "f"(lo.w),
                    "f"(hi.x), "f"(hi.y), "f"(hi.z), "f"(hi.w)
                 : "memory");
}

struct Tile { float4 a0, a1, a2, a3, b0, b1, b2, b3; };

__device__ __forceinline__ void load_tile(const float* p0, const float* p1,
                                          Tile& T)
{
    ldg256(p0,     T.a0, T.a1);
    ldg256(p0 + 8, T.a2, T.a3);
    ldg256(p1,     T.b0, T.b1);
    ldg256(p1 + 8, T.b2, T.b3);
}

__device__ __forceinline__ void compute_store(const Tile& T, float* obase,
                                              size_t sub_stride)
{
    float r0[16] = {T.a0.x,T.a0.y,T.a0.z,T.a0.w, T.a1.x,T.a1.y,T.a1.z,T.a1.w,
                    T.a2.x,T.a2.y,T.a2.z,T.a2.w, T.a3.x,T.a3.y,T.a3.z,T.a3.w};
    float r1[16] = {T.b0.x,T.b0.y,T.b0.z,T.b0.w, T.b1.x,T.b1.y,T.b1.z,T.b1.w,
                    T.b2.x,T.b2.y,T.b2.z,T.b2.w, T.b3.x,T.b3.y,T.b3.z,T.b3.w};

    float ll[8], lh[8], hl[8], hh[8];
#pragma unroll
    for (int k = 0; k < 8; k++) {
        float x00 = r0[2*k], x01 = r0[2*k+1];
        float x10 = r1[2*k], x11 = r1[2*k+1];
        float s0 = x00 + x01, s1 = x10 + x11;
        float d0 = x00 - x01, d1 = x10 - x11;
        ll[k] = (s0 + s1) * 0.5f;
        lh[k] = (s0 - s1) * 0.5f;
        hl[k] = (d0 + d1) * 0.5f;
        hh[k] = (d0 - d1) * 0.5f;
    }

    stg256(obase,
           make_float4(ll[0], ll[1], ll[2], ll[3]),
           make_float4(ll[4], ll[5], ll[6], ll[7]));
    stg256(obase + sub_stride,
           make_float4(lh[0], lh[1], lh[2], lh[3]),
           make_float4(lh[4], lh[5], lh[6], lh[7]));
    stg256(obase + 2 * sub_stride,
           make_float4(hl[0], hl[1], hl[2], hl[3]),
           make_float4(hl[4], hl[5], hl[6], hl[7]));
    stg256(obase + 3 * sub_stride,
           make_float4(hh[0], hh[1], hh[2], hh[3]),
           make_float4(hh[4], hh[5], hh[6], hh[7]));
}

__global__ __launch_bounds__(256) void haar_dwt2_kernel(
    const float* __restrict__ in, float* __restrict__ out)
{
    unsigned t = blockIdx.x * blockDim.x + threadIdx.x;   // 0 .. 2^20-1
    unsigned j8 = t & (GROUPS_PER_ROW - 1);               // 0..31
    unsigned i  = (t >> 5) & (H_OUT - 1);                 // 0..255
    unsigned bc = t >> 13;                                // 0..127 (first tile)

    const float* p0 = in + ((size_t)bc * H_IN + 2u * i) * W_IN + 16u * j8;
    const float* p1 = p0 + W_IN;
    const size_t in_step = (size_t)BC_STRIDE * H_IN * W_IN;

    // output: [B, 4, C, 256, 256]
    unsigned b = bc >> 5;
    unsigned c = bc & 31;
    size_t plane = (size_t)H_OUT * W_OUT;                 // 65536
    size_t sub_stride = (size_t)C_DIM * plane;            // 2,097,152
    float* obase = out + (((size_t)b * 4) * C_DIM + c) * plane
                 + (size_t)i * W_OUT + 8u * j8;           // 32B-aligned
    // Δbc = 128 => Δb = 4, Δc = 0 => constant output step
    const size_t out_step = (size_t)4 * 4 * C_DIM * plane;

    Tile T0, T1;
    load_tile(p0, p1, T0);                       // tile 0 reads in flight
    load_tile(p0 + in_step, p1 + in_step, T1);   // tile 1 reads in flight
    compute_store(T0, obase, sub_stride);        // stores overlap T1's reads
    compute_store(T1, obase + out_step, sub_stride);
}

extern "C" void kernel_launch(void* const* d_in, const int* in_sizes, int n_in,
                              void* d_out, int out_size)
{
    const float* in = (const float*)d_in[0];
    float* out = (float*)d_out;
    // thread-tiles = 8*32*256*32 = 2,097,152; 2 planes/thread -> 1,048,576
    unsigned total_threads = (B_DIM * C_DIM / PLANES_PER_THREAD)
                           * H_OUT * GROUPS_PER_ROW;
    dim3 block(256);
    dim3 grid(total_threads / 256);               // 4096
    haar_dwt2_kernel<<<grid, block>>>(in, out);
}